// round 9
// baseline (speedup 1.0000x reference)
#include <cuda_runtime.h>
#include <cstdint>

#define NNODES 50000
#define NEDGES 800000
#define TOTEDGES (NEDGES + NNODES)
#define NEG_SLOPE 0.2f

// ---------------- scratch (allocation-free: device globals) ----------------
__device__ float g_h0[(size_t)NNODES * 128];
__device__ float g_h1[(size_t)NNODES * 128];
__device__ float g_s[NNODES * 2];
__device__ float g_t[NNODES * 2];
__device__ int   g_deg[NNODES];
__device__ int   g_rowptr[NNODES + 1];
__device__ int   g_cursor[NNODES];
__device__ int   g_col[TOTEDGES];
__device__ int   g_bsum[256];
__device__ int   g_bexc[256];
__device__ float g_Wcat[64 * 128];
__device__ float g_bcat[128];

// ---------------- helpers ----------------
__device__ __forceinline__ uint32_t smem_u32(const void* p) {
    return (uint32_t)__cvta_generic_to_shared(p);
}
typedef unsigned long long ull;
union F4U { float4 f; ull u[2]; };
__device__ __forceinline__ ull splat2(float x) {
    ull r;
    asm("mov.b64 %0, {%1, %1};" : "=l"(r) : "f"(x));
    return r;
}
__device__ __forceinline__ void fma2(ull& d, ull a, ull b) {
    asm("fma.rn.f32x2 %0, %1, %2, %3;" : "=l"(d) : "l"(a), "l"(b), "l"(d));
}
__device__ __forceinline__ void upk2(ull v, float& lo, float& hi) {
    asm("mov.b64 {%0, %1}, %2;" : "=f"(lo), "=f"(hi) : "l"(v));
}
__device__ __forceinline__ void cpa16(uint32_t dst, const void* src) {
    asm volatile("cp.async.cg.shared.global [%0], [%1], 16;" :: "r"(dst), "l"(src));
}

// ---------------- CSR build ----------------
__global__ void k_init_deg(int* __restrict__ deg, int n) {
    int i = blockIdx.x * blockDim.x + threadIdx.x;
    if (i < n) deg[i] = 1;
}
__global__ void k_hist(const int* __restrict__ ei, int e, int* __restrict__ deg) {
    int i = blockIdx.x * blockDim.x + threadIdx.x;
    if (i < e) atomicAdd(&deg[ei[e + i]], 1);
}
__global__ void k_blocksums(const int* __restrict__ deg, int* __restrict__ bsum, int n) {
    __shared__ int wred[8];
    int i = blockIdx.x * 256 + threadIdx.x;
    int v = (i < n) ? deg[i] : 0;
    int lane = threadIdx.x & 31, w = threadIdx.x >> 5;
#pragma unroll
    for (int off = 16; off; off >>= 1) v += __shfl_xor_sync(0xFFFFFFFFu, v, off);
    if (lane == 0) wred[w] = v;
    __syncthreads();
    if (threadIdx.x == 0) {
        int s = 0;
#pragma unroll
        for (int k = 0; k < 8; k++) s += wred[k];
        bsum[blockIdx.x] = s;
    }
}
__global__ void k_scan_top(const int* __restrict__ bsum, int* __restrict__ bexc, int nb) {
    __shared__ int wred[8];
    int tid = threadIdx.x, lane = tid & 31, w = tid >> 5;
    int v = (tid < nb) ? bsum[tid] : 0;
    int x = v;
#pragma unroll
    for (int off = 1; off < 32; off <<= 1) {
        int y = __shfl_up_sync(0xFFFFFFFFu, x, off);
        if (lane >= off) x += y;
    }
    if (lane == 31) wred[w] = x;
    __syncthreads();
    if (w == 0) {
        int sv = (lane < 8) ? wred[lane] : 0;
#pragma unroll
        for (int off = 1; off < 8; off <<= 1) {
            int y = __shfl_up_sync(0xFFFFFFFFu, sv, off);
            if (lane >= off) sv += y;
        }
        if (lane < 8) wred[lane] = sv;
    }
    __syncthreads();
    int woff = (w > 0) ? wred[w - 1] : 0;
    if (tid < nb) bexc[tid] = x + woff - v;
}
__global__ void k_scan_apply(const int* __restrict__ deg, const int* __restrict__ bexc,
                             int* __restrict__ rowptr, int* __restrict__ cursor,
                             int* __restrict__ col, int n) {
    __shared__ int wred[8];
    int i = blockIdx.x * 256 + threadIdx.x;
    int tid = threadIdx.x, lane = tid & 31, w = tid >> 5;
    int v = (i < n) ? deg[i] : 0;
    int x = v;
#pragma unroll
    for (int off = 1; off < 32; off <<= 1) {
        int y = __shfl_up_sync(0xFFFFFFFFu, x, off);
        if (lane >= off) x += y;
    }
    if (lane == 31) wred[w] = x;
    __syncthreads();
    if (w == 0) {
        int sv = (lane < 8) ? wred[lane] : 0;
#pragma unroll
        for (int off = 1; off < 8; off <<= 1) {
            int y = __shfl_up_sync(0xFFFFFFFFu, sv, off);
            if (lane >= off) sv += y;
        }
        if (lane < 8) wred[lane] = sv;
    }
    __syncthreads();
    int woff = (w > 0) ? wred[w - 1] : 0;
    if (i < n) {
        int incl = x + woff + bexc[blockIdx.x];
        rowptr[i + 1] = incl;
        int p = incl - v;
        col[p] = i;
        cursor[i] = p + 1;
        if (i == 0) rowptr[0] = 0;
    }
}
__global__ void k_scatter(const int* __restrict__ ei, int e, int* __restrict__ cursor,
                          int* __restrict__ col) {
    int i = blockIdx.x * blockDim.x + threadIdx.x;
    if (i < e) {
        int s = ei[i];
        int d = ei[e + i];
        int p = atomicAdd(&cursor[d], 1);
        col[p] = s;
    }
}

// ---------------- Wcat prep ----------------
__global__ void k_prep(const float* __restrict__ Wv, const float* __restrict__ bv,
                       const float* __restrict__ Wt, const float* __restrict__ bt,
                       float* __restrict__ Wcat, float* __restrict__ bcat) {
    int i = blockIdx.x * blockDim.x + threadIdx.x;
    if (i < 64 * 128) {
        int k = i >> 7, n = i & 127;
        Wcat[i] = (n < 64) ? Wv[k * 64 + n] : Wt[k * 64 + (n - 64)];
    }
    if (i < 128) bcat[i] = (i < 64) ? bv[i] : bt[i - 64];
}

// ---------------- f32x2 GEMM: 512 threads, 4 rows x (BN/16) cols per thread ----
// Thread (tx,ty): rows ty*4+i (ty<32), cols {g*64 + tx*4 + j} (tx<16).
template <int BN>
__global__ void __launch_bounds__(512, 2) k_gemm(
    const float* __restrict__ A, const float* __restrict__ B,
    float* __restrict__ C, float* __restrict__ C2, int M, int K,
    const float* __restrict__ bias, int relu,
    const float* __restrict__ a_src, const float* __restrict__ a_dst,
    float* __restrict__ s_out, float* __restrict__ t_out)
{
    constexpr int BM = 128, BK = 16, TN = BN / 16;
    constexpr int NG = BN / 64;  // column groups per thread (1 or 2)
    __shared__ float As[2][BM][BK];
    __shared__ float Bs[2][BK][BN];
    __shared__ float sh_att[2 * BN];

    int tid = threadIdx.x;
    int tx = tid & 15, ty = tid >> 4;  // ty 0..31
    int blockRow = blockIdx.x * BM;

    if (a_src) {
        if (tid < BN) sh_att[tid] = a_src[tid];
        else if (tid < 2 * BN) sh_att[tid] = a_dst[tid - BN];
    }

    ull acc[4][TN / 2];
#pragma unroll
    for (int i = 0; i < 4; i++)
#pragma unroll
        for (int j = 0; j < TN / 2; j++) acc[i][j] = 0ull;

    int nch = K / BK;

    auto loadA = [&](int c, int st) {
        int k0 = c * BK;
        // 512 float4 over 512 threads
        int row = tid >> 2, q = tid & 3;
        int gr = blockRow + row;
        if (gr >= M) gr = M - 1;
        cpa16(smem_u32(&As[st][row][q * 4]), &A[(size_t)gr * K + k0 + q * 4]);
    };
    auto loadB = [&](int c, int st) {
        int k0 = c * BK;
        constexpr int CH = BK * BN / 4;  // float4 count: 512 (BN=128) or 256 (BN=64)
        if (CH == 512 || tid < CH) {
            int kr = tid / (BN / 4), q = tid % (BN / 4);
            cpa16(smem_u32(&Bs[st][kr][q * 4]), &B[(size_t)(k0 + kr) * BN + q * 4]);
        }
    };

    loadA(0, 0);
    loadB(0, 0);
    asm volatile("cp.async.commit_group;");

    for (int c = 0; c < nch; c++) {
        int st = c & 1;
        if (c + 1 < nch) {
            loadA(c + 1, (c + 1) & 1);
            loadB(c + 1, (c + 1) & 1);
            asm volatile("cp.async.commit_group;");
            asm volatile("cp.async.wait_group 1;");
        } else {
            asm volatile("cp.async.wait_group 0;");
        }
        __syncthreads();

#pragma unroll
        for (int k4 = 0; k4 < BK; k4 += 4) {
            float4 a4[4];
#pragma unroll
            for (int i = 0; i < 4; i++)
                a4[i] = *reinterpret_cast<const float4*>(&As[st][ty * 4 + i][k4]);
#pragma unroll
            for (int kk = 0; kk < 4; kk++) {
                ull b2[TN / 2];
#pragma unroll
                for (int g = 0; g < NG; g++) {
                    F4U bu;
                    bu.f = *reinterpret_cast<const float4*>(&Bs[st][k4 + kk][g * 64 + tx * 4]);
                    b2[g * 2 + 0] = bu.u[0];
                    b2[g * 2 + 1] = bu.u[1];
                }
#pragma unroll
                for (int i = 0; i < 4; i++) {
                    float av = (kk == 0) ? a4[i].x : (kk == 1) ? a4[i].y : (kk == 2) ? a4[i].z : a4[i].w;
                    ull a2 = splat2(av);
#pragma unroll
                    for (int j = 0; j < TN / 2; j++) fma2(acc[i][j], a2, b2[j]);
                }
            }
        }
        __syncthreads();
    }

    // ---- per-row epilogue ----
#pragma unroll
    for (int i = 0; i < 4; i++) {
        int r = blockRow + ty * 4 + i;
        float af[TN];
#pragma unroll
        for (int j = 0; j < TN / 2; j++) upk2(acc[i][j], af[2 * j], af[2 * j + 1]);

        if (s_out) {
            if (BN == 128) {
                float ps0 = 0.f, pt0 = 0.f, ps1 = 0.f, pt1 = 0.f;
#pragma unroll
                for (int j = 0; j < 4; j++) {
                    int c0 = tx * 4 + j, c1 = 64 + tx * 4 + j;
                    ps0 += af[j] * sh_att[c0];
                    pt0 += af[j] * sh_att[BN + c0];
                    ps1 += af[4 + j] * sh_att[c1];
                    pt1 += af[4 + j] * sh_att[BN + c1];
                }
#pragma unroll
                for (int off = 8; off; off >>= 1) {
                    ps0 += __shfl_xor_sync(0xFFFFFFFFu, ps0, off);
                    pt0 += __shfl_xor_sync(0xFFFFFFFFu, pt0, off);
                    ps1 += __shfl_xor_sync(0xFFFFFFFFu, ps1, off);
                    pt1 += __shfl_xor_sync(0xFFFFFFFFu, pt1, off);
                }
                if (tx == 0 && r < M) {
                    s_out[r * 2 + 0] = ps0;
                    s_out[r * 2 + 1] = ps1;
                    t_out[r * 2 + 0] = pt0;
                    t_out[r * 2 + 1] = pt1;
                }
            } else {
                float ps = 0.f, pt = 0.f;
#pragma unroll
                for (int j = 0; j < 4; j++) {
                    int col = tx * 4 + j;
                    ps += af[j] * sh_att[col];
                    pt += af[j] * sh_att[BN + col];
                }
#pragma unroll
                for (int off = 8; off; off >>= 1) {
                    ps += __shfl_xor_sync(0xFFFFFFFFu, ps, off);
                    pt += __shfl_xor_sync(0xFFFFFFFFu, pt, off);
                }
                if (tx == 0 && r < M) {
                    s_out[r] = ps;
                    t_out[r] = pt;
                }
            }
        }

        if (r < M) {
#pragma unroll
            for (int g = 0; g < NG; g++) {
                int col = g * 64 + tx * 4;
                float4 v;
                v.x = af[g * 4 + 0];
                v.y = af[g * 4 + 1];
                v.z = af[g * 4 + 2];
                v.w = af[g * 4 + 3];
                if (bias) {
                    v.x += bias[col + 0]; v.y += bias[col + 1];
                    v.z += bias[col + 2]; v.w += bias[col + 3];
                }
                if (relu) {
                    v.x = fmaxf(v.x, 0.f); v.y = fmaxf(v.y, 0.f);
                    v.z = fmaxf(v.z, 0.f); v.w = fmaxf(v.w, 0.f);
                }
                if (C2) {
                    float* dst = (g == 0) ? C : C2;
                    *reinterpret_cast<float4*>(&dst[(size_t)r * 64 + tx * 4]) = v;
                } else {
                    *reinterpret_cast<float4*>(&C[(size_t)r * BN + col]) = v;
                }
            }
        }
    }
}

// ---------------- GAT aggregation: one WARP per dst node (online softmax) ----
template <int H, bool RELU>
__global__ void __launch_bounds__(256) k_aggw(const float* __restrict__ hin,
                                              const float* __restrict__ s,
                                              const float* __restrict__ t,
                                              const int* __restrict__ rowptr,
                                              const int* __restrict__ col,
                                              const float* __restrict__ bias,
                                              float* __restrict__ out, int n) {
    constexpr int W = H * 64;
    constexpr int C = W / 32;
    int node = (blockIdx.x * 256 + threadIdx.x) >> 5;
    if (node >= n) return;
    int lane = threadIdx.x & 31;
    int start = rowptr[node];
    int deg = rowptr[node + 1] - start;

    float tn[H];
#pragma unroll
    for (int h = 0; h < H; h++) tn[h] = t[node * H + h];

    // fused pass 1+2: online softmax
    float m[H], sm[H];
#pragma unroll
    for (int h = 0; h < H; h++) { m[h] = -1e30f; sm[h] = 0.f; }
    for (int k = lane; k < deg; k += 32) {
        int src = col[start + k];
        float e[H];
        if (H == 2) {
            float2 sv = *reinterpret_cast<const float2*>(&s[src * 2]);
            e[0] = sv.x + tn[0];
            e[1] = sv.y + tn[1];
        } else {
            e[0] = s[src] + tn[0];
        }
#pragma unroll
        for (int h = 0; h < H; h++) {
            float eh = e[h];
            eh = eh > 0.f ? eh : NEG_SLOPE * eh;
            float old = m[h];
            float nm = fmaxf(old, eh);
            sm[h] = sm[h] * __expf(old - nm) + __expf(eh - nm);
            m[h] = nm;
        }
    }
    float inv[H];
#pragma unroll
    for (int h = 0; h < H; h++) {
#pragma unroll
        for (int off = 16; off; off >>= 1) {
            float mo = __shfl_xor_sync(0xFFFFFFFFu, m[h], off);
            float so = __shfl_xor_sync(0xFFFFFFFFu, sm[h], off);
            float nm = fmaxf(m[h], mo);
            sm[h] = sm[h] * __expf(m[h] - nm) + so * __expf(mo - nm);
            m[h] = nm;
        }
        inv[h] = 1.f / (sm[h] + 1e-16f);
    }

    // pass 3: weighted gather
    float acc[C];
#pragma unroll
    for (int c = 0; c < C; c++) acc[c] = 0.f;
    for (int base = 0; base < deg; base += 32) {
        int k = base + lane;
        int src = 0;
        float al0 = 0.f, al1 = 0.f;
        if (k < deg) {
            src = col[start + k];
            if (H == 2) {
                float2 sv = *reinterpret_cast<const float2*>(&s[src * 2]);
                float e0 = sv.x + tn[0];
                e0 = e0 > 0.f ? e0 : NEG_SLOPE * e0;
                al0 = __expf(e0 - m[0]) * inv[0];
                float e1 = sv.y + tn[1];
                e1 = e1 > 0.f ? e1 : NEG_SLOPE * e1;
                al1 = __expf(e1 - m[1]) * inv[1];
            } else {
                float e = s[src] + tn[0];
                e = e > 0.f ? e : NEG_SLOPE * e;
                al0 = __expf(e - m[0]) * inv[0];
            }
        }
        int nk = min(32, deg - base);
        for (int e2 = 0; e2 < nk; e2++) {
            int sb = __shfl_sync(0xFFFFFFFFu, src, e2);
            float a0 = __shfl_sync(0xFFFFFFFFu, al0, e2);
            float a1 = (H == 2) ? __shfl_sync(0xFFFFFFFFu, al1, e2) : a0;
            const float* hp = hin + (size_t)sb * W;
#pragma unroll
            for (int c = 0; c < C; c++) {
                float a = (H == 2) ? ((c < 2) ? a0 : a1) : a0;
                acc[c] = fmaf(a, hp[lane + 32 * c], acc[c]);
            }
        }
    }

#pragma unroll
    for (int c = 0; c < C; c++) {
        float v = acc[c] + bias[lane + 32 * c];
        if (RELU) v = fmaxf(v, 0.f);
        out[(size_t)node * W + lane + 32 * c] = v;
    }
}

// ---------------- host launch ----------------
extern "C" void kernel_launch(void* const* d_in, const int* in_sizes, int n_in,
                              void* d_out, int out_size) {
    const float* x     = (const float*)d_in[0];
    const int*   ei    = (const int*)d_in[1];
    const float* W0    = (const float*)d_in[2];
    const float* as0   = (const float*)d_in[3];
    const float* ad0   = (const float*)d_in[4];
    const float* b0    = (const float*)d_in[5];
    const float* W1    = (const float*)d_in[6];
    const float* as1   = (const float*)d_in[7];
    const float* ad1   = (const float*)d_in[8];
    const float* b1    = (const float*)d_in[9];
    const float* W2    = (const float*)d_in[10];
    const float* as2   = (const float*)d_in[11];
    const float* ad2   = (const float*)d_in[12];
    const float* b2    = (const float*)d_in[13];
    const float* Wv    = (const float*)d_in[14];
    const float* bv    = (const float*)d_in[15];
    const float* Wt    = (const float*)d_in[16];
    const float* bt    = (const float*)d_in[17];

    int N = in_sizes[0] / 512;
    int E = in_sizes[1] / 2;

    float* out = (float*)d_out;
    float* h_out = out;
    float* vis = out + (size_t)N * 64;
    float* txt = out + (size_t)N * 64 * 2;

    float *h0, *h1, *sA, *tA, *Wcat, *bcat;
    int *deg, *rowptr, *cursor, *colA, *bsum, *bexc;
    cudaGetSymbolAddress((void**)&h0, g_h0);
    cudaGetSymbolAddress((void**)&h1, g_h1);
    cudaGetSymbolAddress((void**)&sA, g_s);
    cudaGetSymbolAddress((void**)&tA, g_t);
    cudaGetSymbolAddress((void**)&deg, g_deg);
    cudaGetSymbolAddress((void**)&rowptr, g_rowptr);
    cudaGetSymbolAddress((void**)&cursor, g_cursor);
    cudaGetSymbolAddress((void**)&colA, g_col);
    cudaGetSymbolAddress((void**)&bsum, g_bsum);
    cudaGetSymbolAddress((void**)&bexc, g_bexc);
    cudaGetSymbolAddress((void**)&Wcat, g_Wcat);
    cudaGetSymbolAddress((void**)&bcat, g_bcat);

    static cudaStream_t s2 = nullptr;
    static cudaEvent_t evFork = nullptr, evJoin = nullptr;
    if (!s2) {
        cudaStreamCreateWithFlags(&s2, cudaStreamNonBlocking);
        cudaEventCreateWithFlags(&evFork, cudaEventDisableTiming);
        cudaEventCreateWithFlags(&evJoin, cudaEventDisableTiming);
    }

    int nb = (N + 255) / 256;
    int gblk = (N + 127) / 128;
    int wgrid = (N * 32 + 255) / 256;

    // ---- fork: CSR build + Wcat prep on side stream ----
    cudaEventRecord(evFork, 0);
    cudaStreamWaitEvent(s2, evFork, 0);
    k_init_deg<<<nb, 256, 0, s2>>>(deg, N);
    k_hist<<<(E + 255) / 256, 256, 0, s2>>>(ei, E, deg);
    k_blocksums<<<nb, 256, 0, s2>>>(deg, bsum, N);
    k_scan_top<<<1, 256, 0, s2>>>(bsum, bexc, nb);
    k_scan_apply<<<nb, 256, 0, s2>>>(deg, bexc, rowptr, cursor, colA, N);
    k_scatter<<<(E + 255) / 256, 256, 0, s2>>>(ei, E, cursor, colA);
    k_prep<<<(64 * 128 + 255) / 256, 256, 0, s2>>>(Wv, bv, Wt, bt, Wcat, bcat);
    cudaEventRecord(evJoin, s2);

    // ---- main stream: layer-0 GEMM concurrently ----
    k_gemm<128><<<gblk, 512>>>(x, W0, h0, nullptr, N, 512, nullptr, 0, as0, ad0, sA, tA);

    // ---- join ----
    cudaStreamWaitEvent(0, evJoin, 0);

    // ---- layer 0 aggregation ----
    k_aggw<2, true><<<wgrid, 256>>>(h0, sA, tA, rowptr, colA, b0, h1, N);

    // ---- layer 1 ----
    k_gemm<128><<<gblk, 512>>>(h1, W1, h0, nullptr, N, 128, nullptr, 0, as1, ad1, sA, tA);
    k_aggw<2, true><<<wgrid, 256>>>(h0, sA, tA, rowptr, colA, b1, h1, N);

    // ---- layer 2 (heads=1, no relu) ----
    k_gemm<64><<<gblk, 512>>>(h1, W2, h0, nullptr, N, 128, nullptr, 0, as2, ad2, sA, tA);
    k_aggw<1, false><<<wgrid, 256>>>(h0, sA, tA, rowptr, colA, b2, h_out, N);

    // ---- MLP heads: one combined GEMM with split store ----
    k_gemm<128><<<gblk, 512>>>(h_out, Wcat, vis, txt, N, 64, bcat, 1,
                               nullptr, nullptr, nullptr, nullptr);
}

// round 10
// speedup vs baseline: 1.1493x; 1.1493x over previous
#include <cuda_runtime.h>
#include <cstdint>

#define NNODES 50000
#define NEDGES 800000
#define TOTEDGES (NEDGES + NNODES)
#define NEG_SLOPE 0.2f

// ---------------- scratch (allocation-free: device globals) ----------------
__device__ float g_h0[(size_t)NNODES * 128];
__device__ float g_h1[(size_t)NNODES * 128];
__device__ float g_s[NNODES * 2];
__device__ float g_t[NNODES * 2];
__device__ int   g_deg[NNODES];
__device__ int   g_rowptr[NNODES + 1];
__device__ int   g_cursor[NNODES];
__device__ int   g_col[TOTEDGES];
__device__ int   g_bsum[256];
__device__ int   g_bexc[256];
__device__ float g_Wcat[64 * 128];
__device__ float g_bcat[128];

// ---------------- helpers ----------------
__device__ __forceinline__ uint32_t smem_u32(const void* p) {
    return (uint32_t)__cvta_generic_to_shared(p);
}
typedef unsigned long long ull;
union F4U { float4 f; ull u[2]; };
__device__ __forceinline__ ull splat2(float x) {
    ull r;
    asm("mov.b64 %0, {%1, %1};" : "=l"(r) : "f"(x));
    return r;
}
__device__ __forceinline__ void fma2(ull& d, ull a, ull b) {
    asm("fma.rn.f32x2 %0, %1, %2, %3;" : "=l"(d) : "l"(a), "l"(b), "l"(d));
}
__device__ __forceinline__ void upk2(ull v, float& lo, float& hi) {
    asm("mov.b64 {%0, %1}, %2;" : "=f"(lo), "=f"(hi) : "l"(v));
}
__device__ __forceinline__ void cpa16(uint32_t dst, const void* src) {
    asm volatile("cp.async.cg.shared.global [%0], [%1], 16;" :: "r"(dst), "l"(src));
}

// ---------------- CSR build ----------------
__global__ void k_init_deg(int* __restrict__ deg, int n) {
    int i = blockIdx.x * blockDim.x + threadIdx.x;
    if (i < n) deg[i] = 1;
}
__global__ void k_hist(const int* __restrict__ ei, int e, int* __restrict__ deg) {
    int i = blockIdx.x * blockDim.x + threadIdx.x;
    if (i < e) atomicAdd(&deg[ei[e + i]], 1);
}
__global__ void k_blocksums(const int* __restrict__ deg, int* __restrict__ bsum, int n) {
    __shared__ int wred[8];
    int i = blockIdx.x * 256 + threadIdx.x;
    int v = (i < n) ? deg[i] : 0;
    int lane = threadIdx.x & 31, w = threadIdx.x >> 5;
#pragma unroll
    for (int off = 16; off; off >>= 1) v += __shfl_xor_sync(0xFFFFFFFFu, v, off);
    if (lane == 0) wred[w] = v;
    __syncthreads();
    if (threadIdx.x == 0) {
        int s = 0;
#pragma unroll
        for (int k = 0; k < 8; k++) s += wred[k];
        bsum[blockIdx.x] = s;
    }
}
__global__ void k_scan_top(const int* __restrict__ bsum, int* __restrict__ bexc, int nb) {
    __shared__ int wred[8];
    int tid = threadIdx.x, lane = tid & 31, w = tid >> 5;
    int v = (tid < nb) ? bsum[tid] : 0;
    int x = v;
#pragma unroll
    for (int off = 1; off < 32; off <<= 1) {
        int y = __shfl_up_sync(0xFFFFFFFFu, x, off);
        if (lane >= off) x += y;
    }
    if (lane == 31) wred[w] = x;
    __syncthreads();
    if (w == 0) {
        int sv = (lane < 8) ? wred[lane] : 0;
#pragma unroll
        for (int off = 1; off < 8; off <<= 1) {
            int y = __shfl_up_sync(0xFFFFFFFFu, sv, off);
            if (lane >= off) sv += y;
        }
        if (lane < 8) wred[lane] = sv;
    }
    __syncthreads();
    int woff = (w > 0) ? wred[w - 1] : 0;
    if (tid < nb) bexc[tid] = x + woff - v;
}
__global__ void k_scan_apply(const int* __restrict__ deg, const int* __restrict__ bexc,
                             int* __restrict__ rowptr, int* __restrict__ cursor,
                             int* __restrict__ col, int n) {
    __shared__ int wred[8];
    int i = blockIdx.x * 256 + threadIdx.x;
    int tid = threadIdx.x, lane = tid & 31, w = tid >> 5;
    int v = (i < n) ? deg[i] : 0;
    int x = v;
#pragma unroll
    for (int off = 1; off < 32; off <<= 1) {
        int y = __shfl_up_sync(0xFFFFFFFFu, x, off);
        if (lane >= off) x += y;
    }
    if (lane == 31) wred[w] = x;
    __syncthreads();
    if (w == 0) {
        int sv = (lane < 8) ? wred[lane] : 0;
#pragma unroll
        for (int off = 1; off < 8; off <<= 1) {
            int y = __shfl_up_sync(0xFFFFFFFFu, sv, off);
            if (lane >= off) sv += y;
        }
        if (lane < 8) wred[lane] = sv;
    }
    __syncthreads();
    int woff = (w > 0) ? wred[w - 1] : 0;
    if (i < n) {
        int incl = x + woff + bexc[blockIdx.x];
        rowptr[i + 1] = incl;
        int p = incl - v;
        col[p] = i;
        cursor[i] = p + 1;
        if (i == 0) rowptr[0] = 0;
    }
}
__global__ void k_scatter(const int* __restrict__ ei, int e, int* __restrict__ cursor,
                          int* __restrict__ col) {
    int i = blockIdx.x * blockDim.x + threadIdx.x;
    if (i < e) {
        int s = ei[i];
        int d = ei[e + i];
        int p = atomicAdd(&cursor[d], 1);
        col[p] = s;
    }
}

// ---------------- Wcat prep ----------------
__global__ void k_prep(const float* __restrict__ Wv, const float* __restrict__ bv,
                       const float* __restrict__ Wt, const float* __restrict__ bt,
                       float* __restrict__ Wcat, float* __restrict__ bcat) {
    int i = blockIdx.x * blockDim.x + threadIdx.x;
    if (i < 64 * 128) {
        int k = i >> 7, n = i & 127;
        Wcat[i] = (n < 64) ? Wv[k * 64 + n] : Wt[k * 64 + (n - 64)];
    }
    if (i < 128) bcat[i] = (i < 64) ? bv[i] : bt[i - 64];
}

// ---------------- f32x2 GEMM (R8 shape): 256 threads, 8 rows x (BN/16) cols ----
template <int BN>
__global__ void __launch_bounds__(256, 2) k_gemm(
    const float* __restrict__ A, const float* __restrict__ B,
    float* __restrict__ C, float* __restrict__ C2, int M, int K,
    const float* __restrict__ bias, int relu,
    const float* __restrict__ a_src, const float* __restrict__ a_dst,
    float* __restrict__ s_out, float* __restrict__ t_out)
{
    constexpr int BM = 128, BK = 16, TN = BN / 16;
    constexpr int NG = BN / 64;
    __shared__ float As[2][BM][BK];
    __shared__ float Bs[2][BK][BN];
    __shared__ float sh_att[2 * BN];

    int tid = threadIdx.x;
    int tx = tid & 15, ty = tid >> 4;
    int blockRow = blockIdx.x * BM;

    if (a_src) {
        if (tid < BN) sh_att[tid] = a_src[tid];
        else if (tid < 2 * BN) sh_att[tid] = a_dst[tid - BN];
    }

    ull acc[8][TN / 2];
#pragma unroll
    for (int i = 0; i < 8; i++)
#pragma unroll
        for (int j = 0; j < TN / 2; j++) acc[i][j] = 0ull;

    int nch = K / BK;

    auto loadA = [&](int c, int st) {
        int k0 = c * BK;
#pragma unroll
        for (int l = 0; l < 2; l++) {
            int f = tid + l * 256;
            int row = f >> 2, q = f & 3;
            int gr = blockRow + row;
            if (gr >= M) gr = M - 1;
            cpa16(smem_u32(&As[st][row][q * 4]), &A[(size_t)gr * K + k0 + q * 4]);
        }
    };
    auto loadB = [&](int c, int st) {
        int k0 = c * BK;
        constexpr int CH = BK * BN / 4;
#pragma unroll
        for (int l = 0; l < CH / 256; l++) {
            int f = tid + l * 256;
            int kr = f / (BN / 4), q = f % (BN / 4);
            cpa16(smem_u32(&Bs[st][kr][q * 4]), &B[(size_t)(k0 + kr) * BN + q * 4]);
        }
    };

    loadA(0, 0);
    loadB(0, 0);
    asm volatile("cp.async.commit_group;");

    for (int c = 0; c < nch; c++) {
        int st = c & 1;
        if (c + 1 < nch) {
            loadA(c + 1, (c + 1) & 1);
            loadB(c + 1, (c + 1) & 1);
            asm volatile("cp.async.commit_group;");
            asm volatile("cp.async.wait_group 1;");
        } else {
            asm volatile("cp.async.wait_group 0;");
        }
        __syncthreads();

#pragma unroll
        for (int k4 = 0; k4 < BK; k4 += 4) {
            float4 a4[8];
#pragma unroll
            for (int i = 0; i < 8; i++)
                a4[i] = *reinterpret_cast<const float4*>(&As[st][ty * 8 + i][k4]);
#pragma unroll
            for (int kk = 0; kk < 4; kk++) {
                ull b2[TN / 2];
#pragma unroll
                for (int g = 0; g < NG; g++) {
                    F4U bu;
                    bu.f = *reinterpret_cast<const float4*>(&Bs[st][k4 + kk][g * 64 + tx * 4]);
                    b2[g * 2 + 0] = bu.u[0];
                    b2[g * 2 + 1] = bu.u[1];
                }
#pragma unroll
                for (int i = 0; i < 8; i++) {
                    float av = (kk == 0) ? a4[i].x : (kk == 1) ? a4[i].y : (kk == 2) ? a4[i].z : a4[i].w;
                    ull a2 = splat2(av);
#pragma unroll
                    for (int j = 0; j < TN / 2; j++) fma2(acc[i][j], a2, b2[j]);
                }
            }
        }
        __syncthreads();
    }

    // ---- per-row epilogue ----
#pragma unroll
    for (int i = 0; i < 8; i++) {
        int r = blockRow + ty * 8 + i;
        float af[TN];
#pragma unroll
        for (int j = 0; j < TN / 2; j++) upk2(acc[i][j], af[2 * j], af[2 * j + 1]);

        if (s_out) {
            if (BN == 128) {
                float ps0 = 0.f, pt0 = 0.f, ps1 = 0.f, pt1 = 0.f;
#pragma unroll
                for (int j = 0; j < 4; j++) {
                    int c0 = tx * 4 + j, c1 = 64 + tx * 4 + j;
                    ps0 += af[j] * sh_att[c0];
                    pt0 += af[j] * sh_att[BN + c0];
                    ps1 += af[4 + j] * sh_att[c1];
                    pt1 += af[4 + j] * sh_att[BN + c1];
                }
#pragma unroll
                for (int off = 8; off; off >>= 1) {
                    ps0 += __shfl_xor_sync(0xFFFFFFFFu, ps0, off);
                    pt0 += __shfl_xor_sync(0xFFFFFFFFu, pt0, off);
                    ps1 += __shfl_xor_sync(0xFFFFFFFFu, ps1, off);
                    pt1 += __shfl_xor_sync(0xFFFFFFFFu, pt1, off);
                }
                if (tx == 0 && r < M) {
                    s_out[r * 2 + 0] = ps0;
                    s_out[r * 2 + 1] = ps1;
                    t_out[r * 2 + 0] = pt0;
                    t_out[r * 2 + 1] = pt1;
                }
            } else {
                float ps = 0.f, pt = 0.f;
#pragma unroll
                for (int j = 0; j < 4; j++) {
                    int col = tx * 4 + j;
                    ps += af[j] * sh_att[col];
                    pt += af[j] * sh_att[BN + col];
                }
#pragma unroll
                for (int off = 8; off; off >>= 1) {
                    ps += __shfl_xor_sync(0xFFFFFFFFu, ps, off);
                    pt += __shfl_xor_sync(0xFFFFFFFFu, pt, off);
                }
                if (tx == 0 && r < M) {
                    s_out[r] = ps;
                    t_out[r] = pt;
                }
            }
        }

        if (r < M) {
#pragma unroll
            for (int g = 0; g < NG; g++) {
                int col = g * 64 + tx * 4;
                float4 v;
                v.x = af[g * 4 + 0];
                v.y = af[g * 4 + 1];
                v.z = af[g * 4 + 2];
                v.w = af[g * 4 + 3];
                if (bias) {
                    v.x += bias[col + 0]; v.y += bias[col + 1];
                    v.z += bias[col + 2]; v.w += bias[col + 3];
                }
                if (relu) {
                    v.x = fmaxf(v.x, 0.f); v.y = fmaxf(v.y, 0.f);
                    v.z = fmaxf(v.z, 0.f); v.w = fmaxf(v.w, 0.f);
                }
                if (C2) {
                    float* dst = (g == 0) ? C : C2;
                    *reinterpret_cast<float4*>(&dst[(size_t)r * 64 + tx * 4]) = v;
                } else {
                    *reinterpret_cast<float4*>(&C[(size_t)r * BN + col]) = v;
                }
            }
        }
    }
}

// ---------------- GAT aggregation: one WARP per dst node ----------------
// Fast path for deg<=32 (>99% of nodes): single read of col/s, alphas in regs.
template <int H, bool RELU>
__global__ void __launch_bounds__(256) k_aggw(const float* __restrict__ hin,
                                              const float* __restrict__ s,
                                              const float* __restrict__ t,
                                              const int* __restrict__ rowptr,
                                              const int* __restrict__ col,
                                              const float* __restrict__ bias,
                                              float* __restrict__ out, int n) {
    constexpr int W = H * 64;
    constexpr int C = W / 32;
    int node = (blockIdx.x * 256 + threadIdx.x) >> 5;
    if (node >= n) return;
    int lane = threadIdx.x & 31;
    int start = rowptr[node];
    int deg = rowptr[node + 1] - start;

    float tn[H];
#pragma unroll
    for (int h = 0; h < H; h++) tn[h] = t[node * H + h];

    float acc[C];
#pragma unroll
    for (int c = 0; c < C; c++) acc[c] = 0.f;

    if (deg <= 32) {
        // ---- single-chunk fast path ----
        int src = 0;
        float e0 = -1e30f, e1 = -1e30f;
        bool act = lane < deg;
        if (act) {
            src = col[start + lane];
            if (H == 2) {
                float2 sv = *reinterpret_cast<const float2*>(&s[src * 2]);
                e0 = sv.x + tn[0];
                e0 = e0 > 0.f ? e0 : NEG_SLOPE * e0;
                e1 = sv.y + tn[1];
                e1 = e1 > 0.f ? e1 : NEG_SLOPE * e1;
            } else {
                e0 = s[src] + tn[0];
                e0 = e0 > 0.f ? e0 : NEG_SLOPE * e0;
            }
        }
        float m0 = e0, m1 = e1;
#pragma unroll
        for (int off = 16; off; off >>= 1) {
            m0 = fmaxf(m0, __shfl_xor_sync(0xFFFFFFFFu, m0, off));
            if (H == 2) m1 = fmaxf(m1, __shfl_xor_sync(0xFFFFFFFFu, m1, off));
        }
        float x0 = act ? __expf(e0 - m0) : 0.f;
        float x1 = (H == 2 && act) ? __expf(e1 - m1) : 0.f;
        float s0 = x0, s1 = x1;
#pragma unroll
        for (int off = 16; off; off >>= 1) {
            s0 += __shfl_xor_sync(0xFFFFFFFFu, s0, off);
            if (H == 2) s1 += __shfl_xor_sync(0xFFFFFFFFu, s1, off);
        }
        float al0 = x0 / (s0 + 1e-16f);
        float al1 = (H == 2) ? x1 / (s1 + 1e-16f) : al0;

        for (int e2 = 0; e2 < deg; e2++) {
            int sb = __shfl_sync(0xFFFFFFFFu, src, e2);
            float a0 = __shfl_sync(0xFFFFFFFFu, al0, e2);
            float a1 = (H == 2) ? __shfl_sync(0xFFFFFFFFu, al1, e2) : a0;
            const float* hp = hin + (size_t)sb * W;
#pragma unroll
            for (int c = 0; c < C; c++) {
                float a = (H == 2) ? ((c < 2) ? a0 : a1) : a0;
                acc[c] = fmaf(a, hp[lane + 32 * c], acc[c]);
            }
        }
    } else {
        // ---- general path: online softmax + rescan ----
        float m[H], sm[H];
#pragma unroll
        for (int h = 0; h < H; h++) { m[h] = -1e30f; sm[h] = 0.f; }
        for (int k = lane; k < deg; k += 32) {
            int src = col[start + k];
            float e[H];
            if (H == 2) {
                float2 sv = *reinterpret_cast<const float2*>(&s[src * 2]);
                e[0] = sv.x + tn[0];
                e[1] = sv.y + tn[1];
            } else {
                e[0] = s[src] + tn[0];
            }
#pragma unroll
            for (int h = 0; h < H; h++) {
                float eh = e[h];
                eh = eh > 0.f ? eh : NEG_SLOPE * eh;
                float old = m[h];
                float nm = fmaxf(old, eh);
                sm[h] = sm[h] * __expf(old - nm) + __expf(eh - nm);
                m[h] = nm;
            }
        }
        float inv[H];
#pragma unroll
        for (int h = 0; h < H; h++) {
#pragma unroll
            for (int off = 16; off; off >>= 1) {
                float mo = __shfl_xor_sync(0xFFFFFFFFu, m[h], off);
                float so = __shfl_xor_sync(0xFFFFFFFFu, sm[h], off);
                float nm = fmaxf(m[h], mo);
                sm[h] = sm[h] * __expf(m[h] - nm) + so * __expf(mo - nm);
                m[h] = nm;
            }
            inv[h] = 1.f / (sm[h] + 1e-16f);
        }

        for (int base = 0; base < deg; base += 32) {
            int k = base + lane;
            int src = 0;
            float al0 = 0.f, al1 = 0.f;
            if (k < deg) {
                src = col[start + k];
                if (H == 2) {
                    float2 sv = *reinterpret_cast<const float2*>(&s[src * 2]);
                    float e0 = sv.x + tn[0];
                    e0 = e0 > 0.f ? e0 : NEG_SLOPE * e0;
                    al0 = __expf(e0 - m[0]) * inv[0];
                    float e1 = sv.y + tn[1];
                    e1 = e1 > 0.f ? e1 : NEG_SLOPE * e1;
                    al1 = __expf(e1 - m[1]) * inv[1];
                } else {
                    float e = s[src] + tn[0];
                    e = e > 0.f ? e : NEG_SLOPE * e;
                    al0 = __expf(e - m[0]) * inv[0];
                }
            }
            int nk = min(32, deg - base);
            for (int e2 = 0; e2 < nk; e2++) {
                int sb = __shfl_sync(0xFFFFFFFFu, src, e2);
                float a0 = __shfl_sync(0xFFFFFFFFu, al0, e2);
                float a1 = (H == 2) ? __shfl_sync(0xFFFFFFFFu, al1, e2) : a0;
                const float* hp = hin + (size_t)sb * W;
#pragma unroll
                for (int c = 0; c < C; c++) {
                    float a = (H == 2) ? ((c < 2) ? a0 : a1) : a0;
                    acc[c] = fmaf(a, hp[lane + 32 * c], acc[c]);
                }
            }
        }
    }

#pragma unroll
    for (int c = 0; c < C; c++) {
        float v = acc[c] + bias[lane + 32 * c];
        if (RELU) v = fmaxf(v, 0.f);
        out[(size_t)node * W + lane + 32 * c] = v;
    }
}

// ---------------- host launch ----------------
extern "C" void kernel_launch(void* const* d_in, const int* in_sizes, int n_in,
                              void* d_out, int out_size) {
    const float* x     = (const float*)d_in[0];
    const int*   ei    = (const int*)d_in[1];
    const float* W0    = (const float*)d_in[2];
    const float* as0   = (const float*)d_in[3];
    const float* ad0   = (const float*)d_in[4];
    const float* b0    = (const float*)d_in[5];
    const float* W1    = (const float*)d_in[6];
    const float* as1   = (const float*)d_in[7];
    const float* ad1   = (const float*)d_in[8];
    const float* b1    = (const float*)d_in[9];
    const float* W2    = (const float*)d_in[10];
    const float* as2   = (const float*)d_in[11];
    const float* ad2   = (const float*)d_in[12];
    const float* b2    = (const float*)d_in[13];
    const float* Wv    = (const float*)d_in[14];
    const float* bv    = (const float*)d_in[15];
    const float* Wt    = (const float*)d_in[16];
    const float* bt    = (const float*)d_in[17];

    int N = in_sizes[0] / 512;
    int E = in_sizes[1] / 2;

    float* out = (float*)d_out;
    float* h_out = out;
    float* vis = out + (size_t)N * 64;
    float* txt = out + (size_t)N * 64 * 2;

    float *h0, *h1, *sA, *tA, *Wcat, *bcat;
    int *deg, *rowptr, *cursor, *colA, *bsum, *bexc;
    cudaGetSymbolAddress((void**)&h0, g_h0);
    cudaGetSymbolAddress((void**)&h1, g_h1);
    cudaGetSymbolAddress((void**)&sA, g_s);
    cudaGetSymbolAddress((void**)&tA, g_t);
    cudaGetSymbolAddress((void**)&deg, g_deg);
    cudaGetSymbolAddress((void**)&rowptr, g_rowptr);
    cudaGetSymbolAddress((void**)&cursor, g_cursor);
    cudaGetSymbolAddress((void**)&colA, g_col);
    cudaGetSymbolAddress((void**)&bsum, g_bsum);
    cudaGetSymbolAddress((void**)&bexc, g_bexc);
    cudaGetSymbolAddress((void**)&Wcat, g_Wcat);
    cudaGetSymbolAddress((void**)&bcat, g_bcat);

    static cudaStream_t s2 = nullptr;
    static cudaEvent_t evFork = nullptr, evJoin = nullptr;
    if (!s2) {
        cudaStreamCreateWithFlags(&s2, cudaStreamNonBlocking);
        cudaEventCreateWithFlags(&evFork, cudaEventDisableTiming);
        cudaEventCreateWithFlags(&evJoin, cudaEventDisableTiming);
    }

    int nb = (N + 255) / 256;
    int gblk = (N + 127) / 128;
    int wgrid = (N * 32 + 255) / 256;

    // ---- fork: CSR build + Wcat prep on side stream ----
    cudaEventRecord(evFork, 0);
    cudaStreamWaitEvent(s2, evFork, 0);
    k_init_deg<<<nb, 256, 0, s2>>>(deg, N);
    k_hist<<<(E + 255) / 256, 256, 0, s2>>>(ei, E, deg);
    k_blocksums<<<nb, 256, 0, s2>>>(deg, bsum, N);
    k_scan_top<<<1, 256, 0, s2>>>(bsum, bexc, nb);
    k_scan_apply<<<nb, 256, 0, s2>>>(deg, bexc, rowptr, cursor, colA, N);
    k_scatter<<<(E + 255) / 256, 256, 0, s2>>>(ei, E, cursor, colA);
    k_prep<<<(64 * 128 + 255) / 256, 256, 0, s2>>>(Wv, bv, Wt, bt, Wcat, bcat);
    cudaEventRecord(evJoin, s2);

    // ---- main stream: layer-0 GEMM concurrently ----
    k_gemm<128><<<gblk, 256>>>(x, W0, h0, nullptr, N, 512, nullptr, 0, as0, ad0, sA, tA);

    // ---- join ----
    cudaStreamWaitEvent(0, evJoin, 0);

    // ---- layer 0 aggregation ----
    k_aggw<2, true><<<wgrid, 256>>>(h0, sA, tA, rowptr, colA, b0, h1, N);

    // ---- layer 1 ----
    k_gemm<128><<<gblk, 256>>>(h1, W1, h0, nullptr, N, 128, nullptr, 0, as1, ad1, sA, tA);
    k_aggw<2, true><<<wgrid, 256>>>(h0, sA, tA, rowptr, colA, b1, h1, N);

    // ---- layer 2 (heads=1, no relu) ----
    k_gemm<64><<<gblk, 256>>>(h1, W2, h0, nullptr, N, 128, nullptr, 0, as2, ad2, sA, tA);
    k_aggw<1, false><<<wgrid, 256>>>(h0, sA, tA, rowptr, colA, b2, h_out, N);

    // ---- MLP heads: one combined GEMM with split store ----
    k_gemm<128><<<gblk, 256>>>(h_out, Wcat, vis, txt, N, 64, bcat, 1,
                               nullptr, nullptr, nullptr, nullptr);
}